// round 1
// baseline (speedup 1.0000x reference)
#include <cuda_runtime.h>
#include <cuda_bf16.h>

#define N_NODES 50000
#define N_EDGES 625000
#define IN_DIM  512
#define HID     128
#define OUT_DIM 40
#define N_LAYERS 3

// ---------------- scratch (static device allocations are allowed) ----------
__device__ float g_h[N_NODES * HID];     // node features after each stage
__device__ float g_z[N_NODES * HID];     // z = h + agg
__device__ int   g_deg[N_NODES];
__device__ int   g_off[N_NODES];
__device__ int   g_cur[N_NODES];
__device__ int   g_esrc[N_EDGES];
__device__ float g_ew[N_EDGES];

// ---------------- CSR build ------------------------------------------------
__global__ void zero_deg_kernel() {
    int i = blockIdx.x * blockDim.x + threadIdx.x;
    if (i < N_NODES) g_deg[i] = 0;
}

__global__ void hist_kernel(const int* __restrict__ dst) {
    int e = blockIdx.x * blockDim.x + threadIdx.x;
    if (e < N_EDGES) atomicAdd(&g_deg[dst[e]], 1);
}

__global__ void scan_kernel() {
    __shared__ int s[1024];
    __shared__ int carry_s;
    int t = threadIdx.x;
    if (t == 0) carry_s = 0;
    __syncthreads();
    for (int base = 0; base < N_NODES; base += 1024) {
        int i = base + t;
        int v = (i < N_NODES) ? g_deg[i] : 0;
        s[t] = v;
        __syncthreads();
        for (int d = 1; d < 1024; d <<= 1) {
            int tmp = (t >= d) ? s[t - d] : 0;
            __syncthreads();
            s[t] += tmp;
            __syncthreads();
        }
        int excl = s[t] - v + carry_s;   // read carry before update
        if (i < N_NODES) { g_off[i] = excl; g_cur[i] = excl; }
        __syncthreads();
        if (t == 1023) carry_s += s[1023];
        __syncthreads();
    }
}

__global__ void scatter_kernel(const int* __restrict__ src,
                               const int* __restrict__ dst,
                               const float* __restrict__ ew) {
    int e = blockIdx.x * blockDim.x + threadIdx.x;
    if (e < N_EDGES) {
        int d = dst[e];
        int pos = atomicAdd(&g_cur[d], 1);
        g_esrc[pos] = src[e];
        g_ew[pos]   = ew[e];
    }
}

// ---------------- embedding GEMM: C[M,128] = A[M,512] @ B[512,128] + bias --
__global__ void emb_gemm_kernel(const float* __restrict__ A,
                                const float* __restrict__ B,
                                const float* __restrict__ bias,
                                int M) {
    __shared__ float As[8][132];   // As[kk][m]
    __shared__ float Bs[8][132];   // Bs[kk][n]
    const int tx = threadIdx.x & 15;
    const int ty = threadIdx.x >> 4;
    const int row0 = blockIdx.x * 128;

    float acc[8][8];
#pragma unroll
    for (int i = 0; i < 8; i++)
#pragma unroll
        for (int j = 0; j < 8; j++) acc[i][j] = 0.f;

    for (int kb = 0; kb < IN_DIM; kb += 8) {
#pragma unroll
        for (int e = threadIdx.x; e < 1024; e += 256) {
            int m = e >> 3, kk = e & 7;
            int r = row0 + m;
            As[kk][m] = (r < M) ? A[(size_t)r * IN_DIM + kb + kk] : 0.f;
        }
#pragma unroll
        for (int e = threadIdx.x; e < 1024; e += 256) {
            int kk = e >> 7, n = e & 127;
            Bs[kk][n] = B[(size_t)(kb + kk) * HID + n];
        }
        __syncthreads();
#pragma unroll
        for (int kk = 0; kk < 8; kk++) {
            const float4* pa = (const float4*)(&As[kk][ty * 8]);
            const float4* pb = (const float4*)(&Bs[kk][tx * 8]);
            float4 a0 = pa[0], a1 = pa[1];
            float4 b0 = pb[0], b1 = pb[1];
            float av[8] = {a0.x, a0.y, a0.z, a0.w, a1.x, a1.y, a1.z, a1.w};
            float bv[8] = {b0.x, b0.y, b0.z, b0.w, b1.x, b1.y, b1.z, b1.w};
#pragma unroll
            for (int i = 0; i < 8; i++)
#pragma unroll
                for (int j = 0; j < 8; j++) acc[i][j] += av[i] * bv[j];
        }
        __syncthreads();
    }
#pragma unroll
    for (int i = 0; i < 8; i++) {
        int r = row0 + ty * 8 + i;
        if (r < M) {
#pragma unroll
            for (int j = 0; j < 8; j++) {
                int n = tx * 8 + j;
                g_h[(size_t)r * HID + n] = acc[i][j] + bias[n];
            }
        }
    }
}

// ---------------- aggregation: z = h + sum_{u->i} w * h[u] -----------------
__global__ void agg_kernel() {
    int node = (blockIdx.x * blockDim.x + threadIdx.x) >> 5;
    int lane = threadIdx.x & 31;
    if (node >= N_NODES) return;
    int s = g_off[node];
    int d = g_deg[node];
    float4 acc = make_float4(0.f, 0.f, 0.f, 0.f);
    for (int i = 0; i < d; i++) {
        int u   = g_esrc[s + i];
        float w = g_ew[s + i];
        float4 hv = *(const float4*)(g_h + (size_t)u * HID + lane * 4);
        acc.x += w * hv.x; acc.y += w * hv.y;
        acc.z += w * hv.z; acc.w += w * hv.w;
    }
    float4 hv = *(const float4*)(g_h + (size_t)node * HID + lane * 4);
    acc.x += hv.x; acc.y += hv.y; acc.z += hv.z; acc.w += hv.w;
    *(float4*)(g_z + (size_t)node * HID + lane * 4) = acc;
}

// ---------------- fused MLP: h = relu(relu(z@W1+b1)@W2+b2) -----------------
// dyn smem: zs[128][132] (k-major activations) + ws[128][132] (k-major W)
__global__ void mlp_kernel(const float* __restrict__ W1,
                           const float* __restrict__ b1,
                           const float* __restrict__ W2,
                           const float* __restrict__ b2,
                           int M) {
    extern __shared__ float sm[];
    float* zs = sm;                 // [128][132]
    float* ws = sm + 128 * 132;     // [128][132]
    const int tx = threadIdx.x & 15;
    const int ty = threadIdx.x >> 4;
    const int row0 = blockIdx.x * 128;

    // stage z (transposed to k-major) and W1 (already k-major row layout)
    for (int e = threadIdx.x; e < 128 * 128; e += 256) {
        int k = e & 127, m = e >> 7;
        int r = row0 + m;
        zs[k * 132 + m] = (r < M) ? g_z[(size_t)r * HID + k] : 0.f;
        ws[(e >> 7) * 132 + (e & 127)] = W1[e];
    }
    __syncthreads();

    float acc[8][8];
#pragma unroll
    for (int i = 0; i < 8; i++)
#pragma unroll
        for (int j = 0; j < 8; j++) acc[i][j] = 0.f;

#pragma unroll 4
    for (int k = 0; k < 128; k++) {
        const float4* pa = (const float4*)(zs + k * 132 + ty * 8);
        const float4* pb = (const float4*)(ws + k * 132 + tx * 8);
        float4 a0 = pa[0], a1 = pa[1];
        float4 b0 = pb[0], b1v = pb[1];
        float av[8] = {a0.x, a0.y, a0.z, a0.w, a1.x, a1.y, a1.z, a1.w};
        float bv[8] = {b0.x, b0.y, b0.z, b0.w, b1v.x, b1v.y, b1v.z, b1v.w};
#pragma unroll
        for (int i = 0; i < 8; i++)
#pragma unroll
            for (int j = 0; j < 8; j++) acc[i][j] += av[i] * bv[j];
    }
    __syncthreads();   // everyone done reading zs/ws

    // relu(acc + b1), write transposed into zs, stage W2 into ws
    float bb[8];
#pragma unroll
    for (int j = 0; j < 8; j++) bb[j] = b1[tx * 8 + j];
#pragma unroll
    for (int j = 0; j < 8; j++) {
        int k2 = tx * 8 + j;
#pragma unroll
        for (int i = 0; i < 8; i++) {
            float v = acc[i][j] + bb[j];
            zs[k2 * 132 + ty * 8 + i] = v > 0.f ? v : 0.f;
        }
    }
    for (int e = threadIdx.x; e < 128 * 128; e += 256)
        ws[(e >> 7) * 132 + (e & 127)] = W2[e];
    __syncthreads();

#pragma unroll
    for (int i = 0; i < 8; i++)
#pragma unroll
        for (int j = 0; j < 8; j++) acc[i][j] = 0.f;

#pragma unroll 4
    for (int k = 0; k < 128; k++) {
        const float4* pa = (const float4*)(zs + k * 132 + ty * 8);
        const float4* pb = (const float4*)(ws + k * 132 + tx * 8);
        float4 a0 = pa[0], a1 = pa[1];
        float4 b0 = pb[0], b1v = pb[1];
        float av[8] = {a0.x, a0.y, a0.z, a0.w, a1.x, a1.y, a1.z, a1.w};
        float bv[8] = {b0.x, b0.y, b0.z, b0.w, b1v.x, b1v.y, b1v.z, b1v.w};
#pragma unroll
        for (int i = 0; i < 8; i++)
#pragma unroll
            for (int j = 0; j < 8; j++) acc[i][j] += av[i] * bv[j];
    }

#pragma unroll
    for (int j = 0; j < 8; j++) bb[j] = b2[tx * 8 + j];
#pragma unroll
    for (int i = 0; i < 8; i++) {
        int r = row0 + ty * 8 + i;
        if (r < M) {
#pragma unroll
            for (int j = 0; j < 8; j++) {
                float v = acc[i][j] + bb[j];
                g_h[(size_t)r * HID + tx * 8 + j] = v > 0.f ? v : 0.f;
            }
        }
    }
}

// ---------------- readout: out[M,40] = h @ ro_W + ro_b ---------------------
// dyn smem: hs[128][132] + wt[40][132] (wt[c][k] = ro_W[k*40+c])
__global__ void readout_kernel(const float* __restrict__ Wr,
                               const float* __restrict__ br,
                               float* __restrict__ out, int M) {
    extern __shared__ float sm[];
    float* hs = sm;                 // [128][132]
    float* wt = sm + 128 * 132;     // [40][132]
    const int row0 = blockIdx.x * 128;
    const int tr = threadIdx.x >> 3;   // 0..31  -> 4 rows each
    const int cg = threadIdx.x & 7;    // 0..7   -> 5 cols each

    for (int e = threadIdx.x; e < 128 * 128; e += 256) {
        int m = e >> 7, k = e & 127;
        int r = row0 + m;
        hs[m * 132 + k] = (r < M) ? g_h[(size_t)r * HID + k] : 0.f;
    }
    for (int e = threadIdx.x; e < 128 * OUT_DIM; e += 256) {
        int k = e / OUT_DIM, c = e % OUT_DIM;
        wt[c * 132 + k] = Wr[e];
    }
    __syncthreads();

    float acc[4][5];
#pragma unroll
    for (int r = 0; r < 4; r++)
#pragma unroll
        for (int c = 0; c < 5; c++) acc[r][c] = 0.f;

    for (int k = 0; k < 128; k += 4) {
        float4 hv[4];
#pragma unroll
        for (int r = 0; r < 4; r++)
            hv[r] = *(const float4*)(hs + (tr * 4 + r) * 132 + k);
#pragma unroll
        for (int c = 0; c < 5; c++) {
            float4 wv = *(const float4*)(wt + (cg * 5 + c) * 132 + k);
#pragma unroll
            for (int r = 0; r < 4; r++) {
                acc[r][c] += hv[r].x * wv.x + hv[r].y * wv.y
                           + hv[r].z * wv.z + hv[r].w * wv.w;
            }
        }
    }

#pragma unroll
    for (int r = 0; r < 4; r++) {
        int row = row0 + tr * 4 + r;
        if (row < M) {
#pragma unroll
            for (int c = 0; c < 5; c++) {
                int col = cg * 5 + c;
                out[(size_t)row * OUT_DIM + col] = acc[r][c] + br[col];
            }
        }
    }
}

// ---------------- launch ----------------------------------------------------
extern "C" void kernel_launch(void* const* d_in, const int* in_sizes, int n_in,
                              void* d_out, int out_size) {
    const float* features = (const float*)d_in[0];
    const int*   src      = (const int*)  d_in[1];
    const int*   dst      = (const int*)  d_in[2];
    const float* edge_w   = (const float*)d_in[3];
    const float* emb_W    = (const float*)d_in[4];
    const float* emb_b    = (const float*)d_in[5];
    const float* W1       = (const float*)d_in[6];
    const float* b1       = (const float*)d_in[7];
    const float* W2       = (const float*)d_in[8];
    const float* b2       = (const float*)d_in[9];
    const float* ro_W     = (const float*)d_in[10];
    const float* ro_b     = (const float*)d_in[11];
    float* out = (float*)d_out;

    const int mlp_smem = 2 * 128 * 132 * (int)sizeof(float);           // 135168
    const int ro_smem  = (128 * 132 + OUT_DIM * 132) * (int)sizeof(float); // 88704
    cudaFuncSetAttribute(mlp_kernel,     cudaFuncAttributeMaxDynamicSharedMemorySize, mlp_smem);
    cudaFuncSetAttribute(readout_kernel, cudaFuncAttributeMaxDynamicSharedMemorySize, ro_smem);

    // CSR build
    zero_deg_kernel<<<(N_NODES + 255) / 256, 256>>>();
    hist_kernel<<<(N_EDGES + 255) / 256, 256>>>(dst);
    scan_kernel<<<1, 1024>>>();
    scatter_kernel<<<(N_EDGES + 255) / 256, 256>>>(src, dst, edge_w);

    // input embedding
    const int gemm_blocks = (N_NODES + 127) / 128;   // 391
    emb_gemm_kernel<<<gemm_blocks, 256>>>(features, emb_W, emb_b, N_NODES);

    // GIN layers
    const int agg_blocks = (N_NODES * 32 + 255) / 256;  // 1 warp / node
    for (int l = 0; l < N_LAYERS; l++) {
        agg_kernel<<<agg_blocks, 256>>>();
        mlp_kernel<<<gemm_blocks, 256, mlp_smem>>>(
            W1 + (size_t)l * HID * HID, b1 + (size_t)l * HID,
            W2 + (size_t)l * HID * HID, b2 + (size_t)l * HID, N_NODES);
    }

    // readout
    readout_kernel<<<gemm_blocks, 256, ro_smem>>>(ro_W, ro_b, out, N_NODES);
}

// round 3
// speedup vs baseline: 1.8637x; 1.8637x over previous
#include <cuda_runtime.h>
#include <cuda_bf16.h>
#include <cstdint>

#define N_NODES 50000
#define N_EDGES 625000
#define IN_DIM  512
#define HID     128
#define OUT_DIM 40
#define N_LAYERS 3
#define NB_SCAN ((N_NODES + 1023) / 1024)

// ---------------- scratch ---------------------------------------------------
__device__ float g_h[N_NODES * HID];
__device__ float g_z[N_NODES * HID];
__device__ float g_t[N_NODES * HID];
__device__ int   g_deg[N_NODES];
__device__ int   g_off[N_NODES];
__device__ int   g_cur[N_NODES];
__device__ int   g_esrc[N_EDGES];
__device__ float g_ew[N_EDGES];
__device__ int   g_bsum[64];
__device__ float g_embWt[HID * IN_DIM];          // [128][512] (n-major, k contig)
__device__ float g_W1t[N_LAYERS * HID * HID];
__device__ float g_W2t[N_LAYERS * HID * HID];

// ---------------- helpers ----------------------------------------------------
__device__ __forceinline__ uint32_t tf32_hi(float x) {
    uint32_t o;
    asm("cvt.rna.tf32.f32 %0, %1;" : "=r"(o) : "f"(x));
    return o;
}
__device__ __forceinline__ void tf32_split(float x, uint32_t& hi, uint32_t& lo) {
    hi = tf32_hi(x);
    lo = tf32_hi(x - __uint_as_float(hi));
}
__device__ __forceinline__ void mma_tf32(float* c, uint32_t a0, uint32_t a1,
                                         uint32_t a2, uint32_t a3,
                                         uint32_t b0, uint32_t b1) {
    asm volatile("mma.sync.aligned.m16n8k8.row.col.f32.tf32.tf32.f32 "
                 "{%0,%1,%2,%3}, {%4,%5,%6,%7}, {%8,%9}, {%0,%1,%2,%3};"
                 : "+f"(c[0]), "+f"(c[1]), "+f"(c[2]), "+f"(c[3])
                 : "r"(a0), "r"(a1), "r"(a2), "r"(a3), "r"(b0), "r"(b1));
}

// ---------------- CSR build -------------------------------------------------
__global__ void zero_deg_kernel() {
    int i = blockIdx.x * blockDim.x + threadIdx.x;
    if (i < N_NODES) g_deg[i] = 0;
}
__global__ void hist_kernel(const int* __restrict__ dst) {
    int e = blockIdx.x * blockDim.x + threadIdx.x;
    if (e < N_EDGES) atomicAdd(&g_deg[dst[e]], 1);
}
__global__ void scan1_kernel() {
    __shared__ int s[1024];
    int t = threadIdx.x;
    int i = blockIdx.x * 1024 + t;
    int v = (i < N_NODES) ? g_deg[i] : 0;
    s[t] = v;
    __syncthreads();
    for (int d = 1; d < 1024; d <<= 1) {
        int tmp = (t >= d) ? s[t - d] : 0;
        __syncthreads();
        s[t] += tmp;
        __syncthreads();
    }
    if (i < N_NODES) g_off[i] = s[t] - v;
    if (t == 1023) g_bsum[blockIdx.x] = s[1023];
}
__global__ void scan2_kernel() {
    if (threadIdx.x == 0) {
        int acc = 0;
        for (int b = 0; b < NB_SCAN; b++) { int x = g_bsum[b]; g_bsum[b] = acc; acc += x; }
    }
}
__global__ void scan3_kernel() {
    int i = blockIdx.x * 1024 + threadIdx.x;
    if (i < N_NODES) {
        int o = g_off[i] + g_bsum[blockIdx.x];
        g_off[i] = o;
        g_cur[i] = o;
    }
}
__global__ void scatter_kernel(const int* __restrict__ src,
                               const int* __restrict__ dst,
                               const float* __restrict__ ew) {
    int e = blockIdx.x * blockDim.x + threadIdx.x;
    if (e < N_EDGES) {
        int d = dst[e];
        int pos = atomicAdd(&g_cur[d], 1);
        g_esrc[pos] = src[e];
        g_ew[pos]   = ew[e];
    }
}

// ---------------- weight transpose: Wt[n][k] = W[k][n] ----------------------
__global__ void transpose_kernel(const float* __restrict__ W, float* __restrict__ Wt,
                                 int K, int N) {
    __shared__ float t[32][33];
    int kb = blockIdx.x * 32, nb = blockIdx.y * 32;
    int x = threadIdx.x, y = threadIdx.y;
    for (int i = y; i < 32; i += 8)
        if (kb + i < K && nb + x < N) t[i][x] = W[(size_t)(kb + i) * N + nb + x];
    __syncthreads();
    for (int i = y; i < 32; i += 8)
        if (nb + i < N && kb + x < K) Wt[(size_t)(nb + i) * K + kb + x] = t[x][i];
}

// ---------------- 3xTF32 mma.sync GEMM: C[M,128]=op(A[M,K]@W[K,128]+b) ------
// Wt: [128][K] pre-transposed. Block tile 128x128, 8 warps (4x2), warp 32x64.
#define KCH 32
#define SMS 36                   // padded k-stride (floats)
__global__ void __launch_bounds__(256)
gemm_mma_kernel(const float* __restrict__ A,
                const float* __restrict__ Wt,
                const float* __restrict__ bias,
                float* __restrict__ C,
                int M, int K, int do_relu) {
    extern __shared__ uint32_t sh[];
    uint32_t* Ah = sh;                    // [128][SMS]
    uint32_t* Al = sh + 128 * SMS;
    uint32_t* Bh = sh + 2 * 128 * SMS;    // [n][k]
    uint32_t* Bl = sh + 3 * 128 * SMS;

    const int tid  = threadIdx.x;
    const int wid  = tid >> 5;
    const int lane = tid & 31;
    const int g    = lane >> 2;   // group 0..7
    const int tg   = lane & 3;    // 0..3
    const int wm   = wid & 3;     // 4 warps in m
    const int wn   = wid >> 2;    // 2 warps in n
    const int row0 = blockIdx.x * 128;

    float c[2][8][4];
#pragma unroll
    for (int mi = 0; mi < 2; mi++)
#pragma unroll
        for (int ni = 0; ni < 8; ni++)
#pragma unroll
            for (int q = 0; q < 4; q++) c[mi][ni][q] = 0.f;

    for (int kc = 0; kc < K; kc += KCH) {
        // stage A chunk [128][32] split hi/lo
#pragma unroll
        for (int it = 0; it < 4; it++) {
            int e = tid + it * 256;           // 0..1023 float4 slots
            int m = e >> 3, j = e & 7;
            int r = row0 + m;
            float4 v = make_float4(0.f, 0.f, 0.f, 0.f);
            if (r < M) v = *(const float4*)(A + (size_t)r * K + kc + j * 4);
            uint32_t h0, l0, h1, l1, h2, l2, h3, l3;
            tf32_split(v.x, h0, l0); tf32_split(v.y, h1, l1);
            tf32_split(v.z, h2, l2); tf32_split(v.w, h3, l3);
            int o = m * SMS + j * 4;
            Ah[o] = h0; Ah[o + 1] = h1; Ah[o + 2] = h2; Ah[o + 3] = h3;
            Al[o] = l0; Al[o + 1] = l1; Al[o + 2] = l2; Al[o + 3] = l3;
        }
        // stage B chunk [128][32]
#pragma unroll
        for (int it = 0; it < 4; it++) {
            int e = tid + it * 256;
            int n = e >> 3, j = e & 7;
            float4 v = *(const float4*)(Wt + (size_t)n * K + kc + j * 4);
            uint32_t h0, l0, h1, l1, h2, l2, h3, l3;
            tf32_split(v.x, h0, l0); tf32_split(v.y, h1, l1);
            tf32_split(v.z, h2, l2); tf32_split(v.w, h3, l3);
            int o = n * SMS + j * 4;
            Bh[o] = h0; Bh[o + 1] = h1; Bh[o + 2] = h2; Bh[o + 3] = h3;
            Bl[o] = l0; Bl[o + 1] = l1; Bl[o + 2] = l2; Bl[o + 3] = l3;
        }
        __syncthreads();

#pragma unroll
        for (int ks = 0; ks < KCH; ks += 8) {
            uint32_t ah[2][4], al[2][4], bh[8][2], bl[8][2];
#pragma unroll
            for (int mi = 0; mi < 2; mi++) {
                int rb = wm * 32 + mi * 16;
                ah[mi][0] = Ah[(rb + g) * SMS + ks + tg];
                ah[mi][1] = Ah[(rb + g + 8) * SMS + ks + tg];
                ah[mi][2] = Ah[(rb + g) * SMS + ks + tg + 4];
                ah[mi][3] = Ah[(rb + g + 8) * SMS + ks + tg + 4];
                al[mi][0] = Al[(rb + g) * SMS + ks + tg];
                al[mi][1] = Al[(rb + g + 8) * SMS + ks + tg];
                al[mi][2] = Al[(rb + g) * SMS + ks + tg + 4];
                al[mi][3] = Al[(rb + g + 8) * SMS + ks + tg + 4];
            }
#pragma unroll
            for (int ni = 0; ni < 8; ni++) {
                int nb = wn * 64 + ni * 8;
                bh[ni][0] = Bh[(nb + g) * SMS + ks + tg];
                bh[ni][1] = Bh[(nb + g) * SMS + ks + tg + 4];
                bl[ni][0] = Bl[(nb + g) * SMS + ks + tg];
                bl[ni][1] = Bl[(nb + g) * SMS + ks + tg + 4];
            }
#pragma unroll
            for (int mi = 0; mi < 2; mi++)
#pragma unroll
                for (int ni = 0; ni < 8; ni++) {
                    mma_tf32(c[mi][ni], ah[mi][0], ah[mi][1], ah[mi][2], ah[mi][3],
                             bh[ni][0], bh[ni][1]);
                    mma_tf32(c[mi][ni], ah[mi][0], ah[mi][1], ah[mi][2], ah[mi][3],
                             bl[ni][0], bl[ni][1]);
                    mma_tf32(c[mi][ni], al[mi][0], al[mi][1], al[mi][2], al[mi][3],
                             bh[ni][0], bh[ni][1]);
                }
        }
        __syncthreads();
    }

    // epilogue
#pragma unroll
    for (int mi = 0; mi < 2; mi++) {
#pragma unroll
        for (int half = 0; half < 2; half++) {
            int row = row0 + wm * 32 + mi * 16 + g + half * 8;
            if (row >= M) continue;
#pragma unroll
            for (int ni = 0; ni < 8; ni++) {
                int col = wn * 64 + ni * 8 + tg * 2;
                float2 o;
                o.x = c[mi][ni][half * 2 + 0] + bias[col];
                o.y = c[mi][ni][half * 2 + 1] + bias[col + 1];
                if (do_relu) {
                    o.x = o.x > 0.f ? o.x : 0.f;
                    o.y = o.y > 0.f ? o.y : 0.f;
                }
                *(float2*)(C + (size_t)row * 128 + col) = o;
            }
        }
    }
}

// ---------------- aggregation: z = h + sum_{u->i} w * h[u] -----------------
__global__ void agg_kernel() {
    int node = (blockIdx.x * blockDim.x + threadIdx.x) >> 5;
    int lane = threadIdx.x & 31;
    if (node >= N_NODES) return;
    int s = g_off[node];
    int d = g_deg[node];
    float4 acc = make_float4(0.f, 0.f, 0.f, 0.f);
    for (int i = 0; i < d; i++) {
        int u   = g_esrc[s + i];
        float w = g_ew[s + i];
        float4 hv = *(const float4*)(g_h + (size_t)u * HID + lane * 4);
        acc.x += w * hv.x; acc.y += w * hv.y;
        acc.z += w * hv.z; acc.w += w * hv.w;
    }
    float4 hv = *(const float4*)(g_h + (size_t)node * HID + lane * 4);
    acc.x += hv.x; acc.y += hv.y; acc.z += hv.z; acc.w += hv.w;
    *(float4*)(g_z + (size_t)node * HID + lane * 4) = acc;
}

// ---------------- readout: out[M,40] = h @ ro_W + ro_b ---------------------
__global__ void readout_kernel(const float* __restrict__ Wr,
                               const float* __restrict__ br,
                               float* __restrict__ out, int M) {
    extern __shared__ float sm[];
    float* hs = sm;                 // [128][132]
    float* wt = sm + 128 * 132;     // [40][132]
    const int row0 = blockIdx.x * 128;
    const int tr = threadIdx.x >> 3;
    const int cg = threadIdx.x & 7;

    for (int e = threadIdx.x; e < 128 * 128; e += 256) {
        int m = e >> 7, k = e & 127;
        int r = row0 + m;
        hs[m * 132 + k] = (r < M) ? g_h[(size_t)r * HID + k] : 0.f;
    }
    for (int e = threadIdx.x; e < 128 * OUT_DIM; e += 256) {
        int k = e / OUT_DIM, c = e % OUT_DIM;
        wt[c * 132 + k] = Wr[e];
    }
    __syncthreads();

    float acc[4][5];
#pragma unroll
    for (int r = 0; r < 4; r++)
#pragma unroll
        for (int c = 0; c < 5; c++) acc[r][c] = 0.f;

    for (int k = 0; k < 128; k += 4) {
        float4 hv[4];
#pragma unroll
        for (int r = 0; r < 4; r++)
            hv[r] = *(const float4*)(hs + (tr * 4 + r) * 132 + k);
#pragma unroll
        for (int c = 0; c < 5; c++) {
            float4 wv = *(const float4*)(wt + (cg * 5 + c) * 132 + k);
#pragma unroll
            for (int r = 0; r < 4; r++)
                acc[r][c] += hv[r].x * wv.x + hv[r].y * wv.y
                           + hv[r].z * wv.z + hv[r].w * wv.w;
        }
    }
#pragma unroll
    for (int r = 0; r < 4; r++) {
        int row = row0 + tr * 4 + r;
        if (row < M) {
#pragma unroll
            for (int c = 0; c < 5; c++) {
                int col = cg * 5 + c;
                out[(size_t)row * OUT_DIM + col] = acc[r][c] + br[col];
            }
        }
    }
}

// ---------------- launch ----------------------------------------------------
extern "C" void kernel_launch(void* const* d_in, const int* in_sizes, int n_in,
                              void* d_out, int out_size) {
    const float* features = (const float*)d_in[0];
    const int*   src      = (const int*)  d_in[1];
    const int*   dst      = (const int*)  d_in[2];
    const float* edge_w   = (const float*)d_in[3];
    const float* emb_W    = (const float*)d_in[4];
    const float* emb_b    = (const float*)d_in[5];
    const float* W1       = (const float*)d_in[6];
    const float* b1       = (const float*)d_in[7];
    const float* W2       = (const float*)d_in[8];
    const float* b2       = (const float*)d_in[9];
    const float* ro_W     = (const float*)d_in[10];
    const float* ro_b     = (const float*)d_in[11];
    float* out = (float*)d_out;

    const int gemm_smem = 4 * 128 * SMS * (int)sizeof(uint32_t);           // 73728
    const int ro_smem   = (128 * 132 + OUT_DIM * 132) * (int)sizeof(float); // 88704
    cudaFuncSetAttribute(gemm_mma_kernel, cudaFuncAttributeMaxDynamicSharedMemorySize, gemm_smem);
    cudaFuncSetAttribute(readout_kernel,  cudaFuncAttributeMaxDynamicSharedMemorySize, ro_smem);

    float* d_h;   cudaGetSymbolAddress((void**)&d_h,   g_h);
    float* d_z;   cudaGetSymbolAddress((void**)&d_z,   g_z);
    float* d_t;   cudaGetSymbolAddress((void**)&d_t,   g_t);
    float* d_eWt; cudaGetSymbolAddress((void**)&d_eWt, g_embWt);
    float* d_W1t; cudaGetSymbolAddress((void**)&d_W1t, g_W1t);
    float* d_W2t; cudaGetSymbolAddress((void**)&d_W2t, g_W2t);

    // CSR build
    zero_deg_kernel<<<(N_NODES + 255) / 256, 256>>>();
    hist_kernel<<<(N_EDGES + 255) / 256, 256>>>(dst);
    scan1_kernel<<<NB_SCAN, 1024>>>();
    scan2_kernel<<<1, 32>>>();
    scan3_kernel<<<NB_SCAN, 1024>>>();
    scatter_kernel<<<(N_EDGES + 255) / 256, 256>>>(src, dst, edge_w);

    // weight transposes
    transpose_kernel<<<dim3(IN_DIM / 32, HID / 32), dim3(32, 8)>>>(emb_W, d_eWt, IN_DIM, HID);
    for (int l = 0; l < N_LAYERS; l++) {
        transpose_kernel<<<dim3(4, 4), dim3(32, 8)>>>(W1 + (size_t)l * HID * HID,
                                                      d_W1t + (size_t)l * HID * HID, HID, HID);
        transpose_kernel<<<dim3(4, 4), dim3(32, 8)>>>(W2 + (size_t)l * HID * HID,
                                                      d_W2t + (size_t)l * HID * HID, HID, HID);
    }

    const int gemm_blocks = (N_NODES + 127) / 128;   // 391
    // input embedding (no relu)
    gemm_mma_kernel<<<gemm_blocks, 256, gemm_smem>>>(features, d_eWt, emb_b, d_h,
                                                     N_NODES, IN_DIM, 0);
    // GIN layers
    const int agg_blocks = (N_NODES * 32 + 255) / 256;
    for (int l = 0; l < N_LAYERS; l++) {
        agg_kernel<<<agg_blocks, 256>>>();
        gemm_mma_kernel<<<gemm_blocks, 256, gemm_smem>>>(
            d_z, d_W1t + (size_t)l * HID * HID, b1 + (size_t)l * HID, d_t, N_NODES, HID, 1);
        gemm_mma_kernel<<<gemm_blocks, 256, gemm_smem>>>(
            d_t, d_W2t + (size_t)l * HID * HID, b2 + (size_t)l * HID, d_h, N_NODES, HID, 1);
    }
    // readout
    readout_kernel<<<gemm_blocks, 256, ro_smem>>>(ro_W, ro_b, out, N_NODES);
}

// round 4
// speedup vs baseline: 2.7805x; 1.4919x over previous
#include <cuda_runtime.h>
#include <cuda_bf16.h>
#include <cstdint>

#define N_NODES 50000
#define N_EDGES 625000
#define IN_DIM  512
#define HID     128
#define OUT_DIM 40
#define N_LAYERS 3
#define NB_SCAN ((N_NODES + 1023) / 1024)

// ---------------- scratch ---------------------------------------------------
__device__ float g_h[N_NODES * HID];
__device__ float g_z[N_NODES * HID];
__device__ int   g_deg[N_NODES];
__device__ int   g_off[N_NODES];
__device__ int   g_cur[N_NODES];
__device__ int   g_esrc[N_EDGES];
__device__ float g_ew[N_EDGES];
__device__ int   g_bsum[64];
// pre-split packed bf16 weights: [n][k2] where word = (bf16(k=2k2+1)<<16)|bf16(k=2k2)
__device__ uint32_t g_eBh[HID * (IN_DIM / 2)];
__device__ uint32_t g_eBl[HID * (IN_DIM / 2)];
__device__ uint32_t g_W1h[N_LAYERS * HID * (HID / 2)];
__device__ uint32_t g_W1l[N_LAYERS * HID * (HID / 2)];
__device__ uint32_t g_W2h[N_LAYERS * HID * (HID / 2)];
__device__ uint32_t g_W2l[N_LAYERS * HID * (HID / 2)];

// ---------------- helpers ----------------------------------------------------
__device__ __forceinline__ void split2(float v0, float v1, uint32_t& hi, uint32_t& lo) {
    uint16_t h0, h1, l0, l1;
    asm("cvt.rn.bf16.f32 %0, %1;" : "=h"(h0) : "f"(v0));
    asm("cvt.rn.bf16.f32 %0, %1;" : "=h"(h1) : "f"(v1));
    float r0 = v0 - __uint_as_float((uint32_t)h0 << 16);
    float r1 = v1 - __uint_as_float((uint32_t)h1 << 16);
    asm("cvt.rn.bf16.f32 %0, %1;" : "=h"(l0) : "f"(r0));
    asm("cvt.rn.bf16.f32 %0, %1;" : "=h"(l1) : "f"(r1));
    hi = ((uint32_t)h1 << 16) | h0;
    lo = ((uint32_t)l1 << 16) | l0;
}
__device__ __forceinline__ void mma_bf16(float* c, uint32_t a0, uint32_t a1,
                                         uint32_t a2, uint32_t a3,
                                         uint32_t b0, uint32_t b1) {
    asm volatile("mma.sync.aligned.m16n8k16.row.col.f32.bf16.bf16.f32 "
                 "{%0,%1,%2,%3}, {%4,%5,%6,%7}, {%8,%9}, {%0,%1,%2,%3};"
                 : "+f"(c[0]), "+f"(c[1]), "+f"(c[2]), "+f"(c[3])
                 : "r"(a0), "r"(a1), "r"(a2), "r"(a3), "r"(b0), "r"(b1));
}

// ---------------- CSR build -------------------------------------------------
__global__ void zero_deg_kernel() {
    int i = blockIdx.x * blockDim.x + threadIdx.x;
    if (i < N_NODES) g_deg[i] = 0;
}
__global__ void hist_kernel(const int* __restrict__ dst) {
    int e = blockIdx.x * blockDim.x + threadIdx.x;
    if (e < N_EDGES) atomicAdd(&g_deg[dst[e]], 1);
}
__global__ void scan1_kernel() {
    __shared__ int s[1024];
    int t = threadIdx.x;
    int i = blockIdx.x * 1024 + t;
    int v = (i < N_NODES) ? g_deg[i] : 0;
    s[t] = v;
    __syncthreads();
    for (int d = 1; d < 1024; d <<= 1) {
        int tmp = (t >= d) ? s[t - d] : 0;
        __syncthreads();
        s[t] += tmp;
        __syncthreads();
    }
    if (i < N_NODES) g_off[i] = s[t] - v;
    if (t == 1023) g_bsum[blockIdx.x] = s[1023];
}
__global__ void scan2_kernel() {
    int lane = threadIdx.x;
    int v0 = (lane < NB_SCAN) ? g_bsum[lane] : 0;
    int v1 = (32 + lane < NB_SCAN) ? g_bsum[32 + lane] : 0;
    int s0 = v0;
    for (int d = 1; d < 32; d <<= 1) {
        int t = __shfl_up_sync(0xffffffffu, s0, d);
        if (lane >= d) s0 += t;
    }
    int tot0 = __shfl_sync(0xffffffffu, s0, 31);
    int s1 = v1;
    for (int d = 1; d < 32; d <<= 1) {
        int t = __shfl_up_sync(0xffffffffu, s1, d);
        if (lane >= d) s1 += t;
    }
    if (lane < NB_SCAN) g_bsum[lane] = s0 - v0;
    if (32 + lane < NB_SCAN) g_bsum[32 + lane] = tot0 + s1 - v1;
}
__global__ void scan3_kernel() {
    int i = blockIdx.x * 1024 + threadIdx.x;
    if (i < N_NODES) {
        int o = g_off[i] + g_bsum[blockIdx.x];
        g_off[i] = o;
        g_cur[i] = o;
    }
}
__global__ void scatter_kernel(const int* __restrict__ src,
                               const int* __restrict__ dst,
                               const float* __restrict__ ew) {
    int e = blockIdx.x * blockDim.x + threadIdx.x;
    if (e < N_EDGES) {
        int d = dst[e];
        int pos = atomicAdd(&g_cur[d], 1);
        g_esrc[pos] = src[e];
        g_ew[pos]   = ew[e];
    }
}

// ---------------- weight prep: split/pack bf16, transposed to [n][k2] -------
__global__ void prep_emb_kernel(const float* __restrict__ W) {   // W[512][128]
    int idx = blockIdx.x * blockDim.x + threadIdx.x;             // 128*256
    int n = idx >> 8, k2 = idx & 255;
    float v0 = W[(size_t)(2 * k2) * HID + n];
    float v1 = W[(size_t)(2 * k2 + 1) * HID + n];
    uint32_t hi, lo;
    split2(v0, v1, hi, lo);
    g_eBh[n * 256 + k2] = hi;
    g_eBl[n * 256 + k2] = lo;
}
__global__ void prep_w_kernel(const float* __restrict__ W1, const float* __restrict__ W2) {
    int idx = blockIdx.x * blockDim.x + threadIdx.x;             // 3*128*64
    if (idx >= N_LAYERS * HID * 64) return;
    int l = idx / (HID * 64);
    int rem = idx - l * HID * 64;
    int n = rem >> 6, k2 = rem & 63;
    const float* w1 = W1 + (size_t)l * HID * HID;
    const float* w2 = W2 + (size_t)l * HID * HID;
    uint32_t hi, lo;
    split2(w1[(2 * k2) * HID + n], w1[(2 * k2 + 1) * HID + n], hi, lo);
    g_W1h[idx] = hi; g_W1l[idx] = lo;
    split2(w2[(2 * k2) * HID + n], w2[(2 * k2 + 1) * HID + n], hi, lo);
    g_W2h[idx] = hi; g_W2l[idx] = lo;
}

// ---------------- emb GEMM: g_h[M,128] = features[M,512] @ embW + b --------
#define ST 36          // uint32 k2-stride for 32-k2 chunks (mod 32 == 4)
__global__ void __launch_bounds__(256)
emb_gemm_kernel(const float* __restrict__ A, const float* __restrict__ bias, int M) {
    extern __shared__ uint32_t sh[];
    uint32_t* Ah = sh;
    uint32_t* Al = sh + 128 * ST;
    uint32_t* Bh = sh + 2 * 128 * ST;
    uint32_t* Bl = sh + 3 * 128 * ST;

    const int tid = threadIdx.x, lane = tid & 31, wid = tid >> 5;
    const int g = lane >> 2, tg = lane & 3;
    const int wm = wid & 3, wn = wid >> 2;
    const int row0 = blockIdx.x * 128;

    float c[2][8][4];
#pragma unroll
    for (int mi = 0; mi < 2; mi++)
#pragma unroll
        for (int ni = 0; ni < 8; ni++)
#pragma unroll
            for (int q = 0; q < 4; q++) c[mi][ni][q] = 0.f;

    for (int kc = 0; kc < IN_DIM; kc += 64) {
        // stage A chunk [128][64] -> split packed [128][32]
#pragma unroll
        for (int it = 0; it < 8; it++) {
            int e = tid + it * 256;          // 2048 float4
            int m = e >> 4, j = e & 15;
            int r = row0 + m;
            float4 v = make_float4(0.f, 0.f, 0.f, 0.f);
            if (r < M) v = *(const float4*)(A + (size_t)r * IN_DIM + kc + j * 4);
            uint32_t h0, l0, h1, l1;
            split2(v.x, v.y, h0, l0);
            split2(v.z, v.w, h1, l1);
            int o = m * ST + j * 2;
            Ah[o] = h0; Ah[o + 1] = h1;
            Al[o] = l0; Al[o + 1] = l1;
        }
        // stage B chunk from pre-split global [128][256]
        int kc2 = kc >> 1;
#pragma unroll
        for (int it = 0; it < 4; it++) {
            int e = tid + it * 256;          // 1024 uint4
            int n = e >> 3, q = e & 7;
            uint4 vh = *(const uint4*)(g_eBh + n * 256 + kc2 + q * 4);
            uint4 vl = *(const uint4*)(g_eBl + n * 256 + kc2 + q * 4);
            int o = n * ST + q * 4;
            *(uint4*)(Bh + o) = vh;
            *(uint4*)(Bl + o) = vl;
        }
        __syncthreads();

#pragma unroll
        for (int ks2 = 0; ks2 < 32; ks2 += 8) {
            uint32_t ah[2][4], al[2][4], bh[8][2], bl[8][2];
#pragma unroll
            for (int mi = 0; mi < 2; mi++) {
                int rb = wm * 32 + mi * 16;
                ah[mi][0] = Ah[(rb + g) * ST + ks2 + tg];
                ah[mi][1] = Ah[(rb + g + 8) * ST + ks2 + tg];
                ah[mi][2] = Ah[(rb + g) * ST + ks2 + tg + 4];
                ah[mi][3] = Ah[(rb + g + 8) * ST + ks2 + tg + 4];
                al[mi][0] = Al[(rb + g) * ST + ks2 + tg];
                al[mi][1] = Al[(rb + g + 8) * ST + ks2 + tg];
                al[mi][2] = Al[(rb + g) * ST + ks2 + tg + 4];
                al[mi][3] = Al[(rb + g + 8) * ST + ks2 + tg + 4];
            }
#pragma unroll
            for (int ni = 0; ni < 8; ni++) {
                int nb = wn * 64 + ni * 8;
                bh[ni][0] = Bh[(nb + g) * ST + ks2 + tg];
                bh[ni][1] = Bh[(nb + g) * ST + ks2 + tg + 4];
                bl[ni][0] = Bl[(nb + g) * ST + ks2 + tg];
                bl[ni][1] = Bl[(nb + g) * ST + ks2 + tg + 4];
            }
#pragma unroll
            for (int mi = 0; mi < 2; mi++)
#pragma unroll
                for (int ni = 0; ni < 8; ni++) {
                    mma_bf16(c[mi][ni], ah[mi][0], ah[mi][1], ah[mi][2], ah[mi][3],
                             bh[ni][0], bh[ni][1]);
                    mma_bf16(c[mi][ni], ah[mi][0], ah[mi][1], ah[mi][2], ah[mi][3],
                             bl[ni][0], bl[ni][1]);
                    mma_bf16(c[mi][ni], al[mi][0], al[mi][1], al[mi][2], al[mi][3],
                             bh[ni][0], bh[ni][1]);
                }
        }
        __syncthreads();
    }

#pragma unroll
    for (int mi = 0; mi < 2; mi++)
#pragma unroll
        for (int half = 0; half < 2; half++) {
            int row = row0 + wm * 32 + mi * 16 + g + half * 8;
            if (row >= M) continue;
#pragma unroll
            for (int ni = 0; ni < 8; ni++) {
                int col = wn * 64 + ni * 8 + tg * 2;
                float2 o;
                o.x = c[mi][ni][half * 2 + 0] + bias[col];
                o.y = c[mi][ni][half * 2 + 1] + bias[col + 1];
                *(float2*)(g_h + (size_t)row * HID + col) = o;
            }
        }
}

// ---------------- fused MLP: h = relu(relu(z@W1+b1)@W2+b2) ------------------
#define ST2 68         // uint32 stride for 64-k2 rows (mod 32 == 4)
__global__ void __launch_bounds__(256)
mlp_fused_kernel(const uint32_t* __restrict__ W1h, const uint32_t* __restrict__ W1l,
                 const uint32_t* __restrict__ W2h, const uint32_t* __restrict__ W2l,
                 const float* __restrict__ b1, const float* __restrict__ b2, int M) {
    extern __shared__ uint32_t sh[];
    uint32_t* Ah  = sh;
    uint32_t* Al  = sh + 128 * ST2;
    uint32_t* Wh1 = sh + 2 * 128 * ST2;
    uint32_t* Wl1 = sh + 3 * 128 * ST2;
    uint32_t* Wh2 = sh + 4 * 128 * ST2;
    uint32_t* Wl2 = sh + 5 * 128 * ST2;

    const int tid = threadIdx.x, lane = tid & 31, wid = tid >> 5;
    const int g = lane >> 2, tg = lane & 3;
    const int wm = wid & 3, wn = wid >> 2;
    const int row0 = blockIdx.x * 128;

    // stage z [128][128] -> split packed [128][64]
#pragma unroll
    for (int it = 0; it < 16; it++) {
        int e = tid + it * 256;              // 4096 float4
        int m = e >> 5, j = e & 31;
        int r = row0 + m;
        float4 v = make_float4(0.f, 0.f, 0.f, 0.f);
        if (r < M) v = *(const float4*)(g_z + (size_t)r * HID + j * 4);
        uint32_t h0, l0, h1, l1;
        split2(v.x, v.y, h0, l0);
        split2(v.z, v.w, h1, l1);
        int o = m * ST2 + j * 2;
        Ah[o] = h0; Ah[o + 1] = h1;
        Al[o] = l0; Al[o + 1] = l1;
    }
    // stage W1, W2 (pre-split) [128][64]
#pragma unroll
    for (int it = 0; it < 8; it++) {
        int e = tid + it * 256;              // 2048 uint4
        int n = e >> 4, q = e & 15;
        int o = n * ST2 + q * 4;
        *(uint4*)(Wh1 + o) = *(const uint4*)(W1h + n * 64 + q * 4);
        *(uint4*)(Wl1 + o) = *(const uint4*)(W1l + n * 64 + q * 4);
        *(uint4*)(Wh2 + o) = *(const uint4*)(W2h + n * 64 + q * 4);
        *(uint4*)(Wl2 + o) = *(const uint4*)(W2l + n * 64 + q * 4);
    }
    __syncthreads();

    float c[2][8][4];
#pragma unroll
    for (int mi = 0; mi < 2; mi++)
#pragma unroll
        for (int ni = 0; ni < 8; ni++)
#pragma unroll
            for (int q = 0; q < 4; q++) c[mi][ni][q] = 0.f;

    // GEMM1
#pragma unroll
    for (int ks2 = 0; ks2 < 64; ks2 += 8) {
        uint32_t ah[2][4], al[2][4], bh[8][2], bl[8][2];
#pragma unroll
        for (int mi = 0; mi < 2; mi++) {
            int rb = wm * 32 + mi * 16;
            ah[mi][0] = Ah[(rb + g) * ST2 + ks2 + tg];
            ah[mi][1] = Ah[(rb + g + 8) * ST2 + ks2 + tg];
            ah[mi][2] = Ah[(rb + g) * ST2 + ks2 + tg + 4];
            ah[mi][3] = Ah[(rb + g + 8) * ST2 + ks2 + tg + 4];
            al[mi][0] = Al[(rb + g) * ST2 + ks2 + tg];
            al[mi][1] = Al[(rb + g + 8) * ST2 + ks2 + tg];
            al[mi][2] = Al[(rb + g) * ST2 + ks2 + tg + 4];
            al[mi][3] = Al[(rb + g + 8) * ST2 + ks2 + tg + 4];
        }
#pragma unroll
        for (int ni = 0; ni < 8; ni++) {
            int nb = wn * 64 + ni * 8;
            bh[ni][0] = Wh1[(nb + g) * ST2 + ks2 + tg];
            bh[ni][1] = Wh1[(nb + g) * ST2 + ks2 + tg + 4];
            bl[ni][0] = Wl1[(nb + g) * ST2 + ks2 + tg];
            bl[ni][1] = Wl1[(nb + g) * ST2 + ks2 + tg + 4];
        }
#pragma unroll
        for (int mi = 0; mi < 2; mi++)
#pragma unroll
            for (int ni = 0; ni < 8; ni++) {
                mma_bf16(c[mi][ni], ah[mi][0], ah[mi][1], ah[mi][2], ah[mi][3],
                         bh[ni][0], bh[ni][1]);
                mma_bf16(c[mi][ni], ah[mi][0], ah[mi][1], ah[mi][2], ah[mi][3],
                         bl[ni][0], bl[ni][1]);
                mma_bf16(c[mi][ni], al[mi][0], al[mi][1], al[mi][2], al[mi][3],
                         bh[ni][0], bh[ni][1]);
            }
    }
    __syncthreads();   // all warps done reading Ah/Al

    // relu(c + b1) -> split -> back into Ah/Al
#pragma unroll
    for (int mi = 0; mi < 2; mi++)
#pragma unroll
        for (int ni = 0; ni < 8; ni++) {
            int col = wn * 64 + ni * 8 + tg * 2;
            float bb0 = b1[col], bb1 = b1[col + 1];
            int k2 = wn * 32 + ni * 4 + tg;
            int r0 = wm * 32 + mi * 16 + g;
            uint32_t hi, lo;
            split2(fmaxf(c[mi][ni][0] + bb0, 0.f), fmaxf(c[mi][ni][1] + bb1, 0.f), hi, lo);
            Ah[r0 * ST2 + k2] = hi; Al[r0 * ST2 + k2] = lo;
            split2(fmaxf(c[mi][ni][2] + bb0, 0.f), fmaxf(c[mi][ni][3] + bb1, 0.f), hi, lo);
            Ah[(r0 + 8) * ST2 + k2] = hi; Al[(r0 + 8) * ST2 + k2] = lo;
        }
    __syncthreads();

#pragma unroll
    for (int mi = 0; mi < 2; mi++)
#pragma unroll
        for (int ni = 0; ni < 8; ni++)
#pragma unroll
            for (int q = 0; q < 4; q++) c[mi][ni][q] = 0.f;

    // GEMM2
#pragma unroll
    for (int ks2 = 0; ks2 < 64; ks2 += 8) {
        uint32_t ah[2][4], al[2][4], bh[8][2], bl[8][2];
#pragma unroll
        for (int mi = 0; mi < 2; mi++) {
            int rb = wm * 32 + mi * 16;
            ah[mi][0] = Ah[(rb + g) * ST2 + ks2 + tg];
            ah[mi][1] = Ah[(rb + g + 8) * ST2 + ks2 + tg];
            ah[mi][2] = Ah[(rb + g) * ST2 + ks2 + tg + 4];
            ah[mi][3] = Ah[(rb + g + 8) * ST2 + ks2 + tg + 4];
            al[mi][0] = Al[(rb + g) * ST2 + ks2 + tg];
            al[mi][1] = Al[(rb + g + 8) * ST2 + ks2 + tg];
            al[mi][2] = Al[(rb + g) * ST2 + ks2 + tg + 4];
            al[mi][3] = Al[(rb + g + 8) * ST2 + ks2 + tg + 4];
        }
#pragma unroll
        for (int ni = 0; ni < 8; ni++) {
            int nb = wn * 64 + ni * 8;
            bh[ni][0] = Wh2[(nb + g) * ST2 + ks2 + tg];
            bh[ni][1] = Wh2[(nb + g) * ST2 + ks2 + tg + 4];
            bl[ni][0] = Wl2[(nb + g) * ST2 + ks2 + tg];
            bl[ni][1] = Wl2[(nb + g) * ST2 + ks2 + tg + 4];
        }
#pragma unroll
        for (int mi = 0; mi < 2; mi++)
#pragma unroll
            for (int ni = 0; ni < 8; ni++) {
                mma_bf16(c[mi][ni], ah[mi][0], ah[mi][1], ah[mi][2], ah[mi][3],
                         bh[ni][0], bh[ni][1]);
                mma_bf16(c[mi][ni], ah[mi][0], ah[mi][1], ah[mi][2], ah[mi][3],
                         bl[ni][0], bl[ni][1]);
                mma_bf16(c[mi][ni], al[mi][0], al[mi][1], al[mi][2], al[mi][3],
                         bh[ni][0], bh[ni][1]);
            }
    }

    // epilogue: relu(c + b2) -> g_h
#pragma unroll
    for (int mi = 0; mi < 2; mi++)
#pragma unroll
        for (int half = 0; half < 2; half++) {
            int row = row0 + wm * 32 + mi * 16 + g + half * 8;
            if (row >= M) continue;
#pragma unroll
            for (int ni = 0; ni < 8; ni++) {
                int col = wn * 64 + ni * 8 + tg * 2;
                float2 o;
                o.x = fmaxf(c[mi][ni][half * 2 + 0] + b2[col], 0.f);
                o.y = fmaxf(c[mi][ni][half * 2 + 1] + b2[col + 1], 0.f);
                *(float2*)(g_h + (size_t)row * HID + col) = o;
            }
        }
}

// ---------------- aggregation: z = h + sum_{u->i} w * h[u] -----------------
__global__ void agg_kernel() {
    int node = (blockIdx.x * blockDim.x + threadIdx.x) >> 5;
    int lane = threadIdx.x & 31;
    if (node >= N_NODES) return;
    int s = g_off[node];
    int d = g_deg[node];
    float4 acc = make_float4(0.f, 0.f, 0.f, 0.f);
    for (int i = 0; i < d; i++) {
        int u   = g_esrc[s + i];
        float w = g_ew[s + i];
        float4 hv = *(const float4*)(g_h + (size_t)u * HID + lane * 4);
        acc.x += w * hv.x; acc.y += w * hv.y;
        acc.z += w * hv.z; acc.w += w * hv.w;
    }
    float4 hv = *(const float4*)(g_h + (size_t)node * HID + lane * 4);
    acc.x += hv.x; acc.y += hv.y; acc.z += hv.z; acc.w += hv.w;
    *(float4*)(g_z + (size_t)node * HID + lane * 4) = acc;
}

// ---------------- readout: out[M,40] = h @ ro_W + ro_b ---------------------
__global__ void readout_kernel(const float* __restrict__ Wr,
                               const float* __restrict__ br,
                               float* __restrict__ out, int M) {
    extern __shared__ float sm[];
    float* hs = sm;                 // [128][132]
    float* wt = sm + 128 * 132;     // [40][132]
    const int row0 = blockIdx.x * 128;
    const int tr = threadIdx.x >> 3;
    const int cg = threadIdx.x & 7;

    for (int e = threadIdx.x; e < 128 * 128; e += 256) {
        int m = e >> 7, k = e & 127;
        int r = row0 + m;
        hs[m * 132 + k] = (r < M) ? g_h[(size_t)r * HID + k] : 0.f;
    }
    for (int e = threadIdx.x; e < 128 * OUT_DIM; e += 256) {
        int k = e / OUT_DIM, c = e % OUT_DIM;
        wt[c * 132 + k] = Wr[e];
    }
    __syncthreads();

    float acc[4][5];
#pragma unroll
    for (int r = 0; r < 4; r++)
#pragma unroll
        for (int c = 0; c < 5; c++) acc[r][c] = 0.f;

    for (int k = 0; k < 128; k += 4) {
        float4 hv[4];
#pragma unroll
        for (int r = 0; r < 4; r++)
            hv[r] = *(const float4*)(hs + (tr * 4 + r) * 132 + k);
#pragma unroll
        for (int c = 0; c < 5; c++) {
            float4 wv = *(const float4*)(wt + (cg * 5 + c) * 132 + k);
#pragma unroll
            for (int r = 0; r < 4; r++)
                acc[r][c] += hv[r].x * wv.x + hv[r].y * wv.y
                           + hv[r].z * wv.z + hv[r].w * wv.w;
        }
    }
#pragma unroll
    for (int r = 0; r < 4; r++) {
        int row = row0 + tr * 4 + r;
        if (row < M) {
#pragma unroll
            for (int c = 0; c < 5; c++) {
                int col = cg * 5 + c;
                out[(size_t)row * OUT_DIM + col] = acc[r][c] + br[col];
            }
        }
    }
}

// ---------------- launch ----------------------------------------------------
extern "C" void kernel_launch(void* const* d_in, const int* in_sizes, int n_in,
                              void* d_out, int out_size) {
    const float* features = (const float*)d_in[0];
    const int*   src      = (const int*)  d_in[1];
    const int*   dst      = (const int*)  d_in[2];
    const float* edge_w   = (const float*)d_in[3];
    const float* emb_W    = (const float*)d_in[4];
    const float* emb_b    = (const float*)d_in[5];
    const float* W1       = (const float*)d_in[6];
    const float* b1       = (const float*)d_in[7];
    const float* W2       = (const float*)d_in[8];
    const float* b2       = (const float*)d_in[9];
    const float* ro_W     = (const float*)d_in[10];
    const float* ro_b     = (const float*)d_in[11];
    float* out = (float*)d_out;

    const int emb_smem = 4 * 128 * ST  * (int)sizeof(uint32_t);   // 73728
    const int mlp_smem = 6 * 128 * ST2 * (int)sizeof(uint32_t);   // 208896
    const int ro_smem  = (128 * 132 + OUT_DIM * 132) * (int)sizeof(float);
    cudaFuncSetAttribute(emb_gemm_kernel,  cudaFuncAttributeMaxDynamicSharedMemorySize, emb_smem);
    cudaFuncSetAttribute(mlp_fused_kernel, cudaFuncAttributeMaxDynamicSharedMemorySize, mlp_smem);
    cudaFuncSetAttribute(readout_kernel,   cudaFuncAttributeMaxDynamicSharedMemorySize, ro_smem);

    uint32_t *d_W1h, *d_W1l, *d_W2h, *d_W2l;
    cudaGetSymbolAddress((void**)&d_W1h, g_W1h);
    cudaGetSymbolAddress((void**)&d_W1l, g_W1l);
    cudaGetSymbolAddress((void**)&d_W2h, g_W2h);
    cudaGetSymbolAddress((void**)&d_W2l, g_W2l);

    // CSR build
    zero_deg_kernel<<<(N_NODES + 255) / 256, 256>>>();
    hist_kernel<<<(N_EDGES + 255) / 256, 256>>>(dst);
    scan1_kernel<<<NB_SCAN, 1024>>>();
    scan2_kernel<<<1, 32>>>();
    scan3_kernel<<<NB_SCAN, 1024>>>();
    scatter_kernel<<<(N_EDGES + 255) / 256, 256>>>(src, dst, edge_w);

    // weight prep (split/pack bf16)
    prep_emb_kernel<<<HID * 256 / 256, 256>>>(emb_W);
    prep_w_kernel<<<(N_LAYERS * HID * 64 + 255) / 256, 256>>>(W1, W2);

    const int gemm_blocks = (N_NODES + 127) / 128;   // 391
    emb_gemm_kernel<<<gemm_blocks, 256, emb_smem>>>(features, emb_b, N_NODES);

    const int agg_blocks = (N_NODES * 32 + 255) / 256;
    for (int l = 0; l < N_LAYERS; l++) {
        agg_kernel<<<agg_blocks, 256>>>();
        mlp_fused_kernel<<<gemm_blocks, 256, mlp_smem>>>(
            d_W1h + (size_t)l * HID * 64, d_W1l + (size_t)l * HID * 64,
            d_W2h + (size_t)l * HID * 64, d_W2l + (size_t)l * HID * 64,
            b1 + (size_t)l * HID, b2 + (size_t)l * HID, N_NODES);
    }
    readout_kernel<<<gemm_blocks, 256, ro_smem>>>(ro_W, ro_b, out, N_NODES);
}